// round 4
// baseline (speedup 1.0000x reference)
#include <cuda_runtime.h>
#include <cuda_bf16.h>
#include <math.h>

// Eikonal loss, single fused kernel, dual-strip per block, shfl halos.
// (B,1,H,W) = (64,1,512,512) fp32 -> 1 fp32 scalar.

#define H 512
#define W 512
#define W4 (W / 4)
#define ROWS 16
#define THREADS 128
#define MAX_BLOCKS 4096

__device__ float2 g_part[MAX_BLOCKS];
__device__ unsigned int g_ticket;   // zero-init at load; last block resets to 0

__device__ __forceinline__ float sqrt_approx(float x) {
    float r;
    asm("sqrt.approx.f32 %0, %1;" : "=f"(r) : "f"(x));
    return r;
}

// Load one row's 4-pixel window; halos via warp shuffle (predicated scalar
// loads only on warp-edge lanes). Emits scaled S (vertical kernel row sum)
// and D (horizontal difference).
__device__ __forceinline__ void row_sd(const float* __restrict__ row,
                                       int x, int lane,
                                       float* __restrict__ S,
                                       float* __restrict__ D) {
    float4 v = *(const float4*)(row + x);
    float wl = __shfl_up_sync(0xFFFFFFFFu, v.w, 1);
    float wr = __shfl_down_sync(0xFFFFFFFFu, v.x, 1);
    if (lane == 0)  wl = (x == 0)         ? v.x : __ldg(row + x - 1);
    if (lane == 31) wr = (x + 4 >= W)     ? v.w : __ldg(row + x + 4);
    // window w = {wl, v.x, v.y, v.z, v.w, wr}
    D[0] = (v.y - wl)  * 0.125f;
    D[1] = (v.z - v.x) * 0.125f;
    D[2] = (v.w - v.y) * 0.125f;
    D[3] = (wr  - v.z) * 0.125f;
    S[0] = fmaf(2.0f, v.x, wl  + v.y) * 0.125f;
    S[1] = fmaf(2.0f, v.y, v.x + v.z) * 0.125f;
    S[2] = fmaf(2.0f, v.z, v.y + v.w) * 0.125f;
    S[3] = fmaf(2.0f, v.w, v.z + wr ) * 0.125f;
}

__global__ void __launch_bounds__(THREADS, 7) eik_fused_kernel(
    const float* __restrict__ pred,
    const float* __restrict__ reach,
    float* __restrict__ out,
    int nBlocks)
{
    const int lane = threadIdx.x & 31;
    const int x    = threadIdx.x * 4;          // 128 threads cover the row

    // block -> (batch, strip pair). 32 strips/image -> 16 pairs/image.
    const int b   = blockIdx.x >> 4;
    const int pr  = blockIdx.x & 15;
    const int y0A = (pr * 2) * ROWS;
    const int y0B = y0A + ROWS;

    const size_t base = (size_t)b * H * W;
    const float* p = pred + base;
    const float* r = reach + base;

    // rolling scaled row features for both strips
    float SA0[4], SA1[4], SA2[4], DA0[4], DA1[4], DA2[4];
    float SB0[4], SB1[4], SB2[4], DB0[4], DB1[4], DB2[4];

    {
        const int yTA = (y0A > 0) ? (y0A - 1) : 0;
        row_sd(p + (size_t)yTA * W, x, lane, SA0, DA0);
        row_sd(p + (size_t)y0A * W, x, lane, SA1, DA1);
        row_sd(p + (size_t)(y0B - 1) * W, x, lane, SB0, DB0);
        row_sd(p + (size_t)y0B * W, x, lane, SB1, DB1);
    }

    float lsum = 0.0f;
    float lcnt = 0.0f;

    #pragma unroll
    for (int i = 0; i < ROWS; i++) {
        const int yA  = y0A + i;
        const int yB  = y0B + i;
        const int yAb = yA + 1;                          // interior: y0B-1 < H always
        const int yBb = (yB < H - 1) ? (yB + 1) : (H - 1);

        // issue both strips' loads (independent chains)
        row_sd(p + (size_t)yAb * W, x, lane, SA2, DA2);
        row_sd(p + (size_t)yBb * W, x, lane, SB2, DB2);

        float4 rA = *(const float4*)(r + (size_t)yA * W + x);
        float4 rB = *(const float4*)(r + (size_t)yB * W + x);
        const float rvA[4] = {rA.x, rA.y, rA.z, rA.w};
        const float rvB[4] = {rB.x, rB.y, rB.z, rB.w};

        #pragma unroll
        for (int j = 0; j < 4; j++) {
            float gx = fmaf(2.0f, DA1[j], DA0[j] + DA2[j]);
            float gy = SA2[j] - SA0[j];
            float g2 = fmaf(gx, gx, fmaf(gy, gy, 1e-8f));
            float viol = fabsf(sqrt_approx(g2) - 1.0f);
            float msk  = (rvA[j] > 0.5f) ? 1.0f : 0.0f;
            lsum = fmaf(viol, msk, lsum);
            lcnt += msk;
        }
        #pragma unroll
        for (int j = 0; j < 4; j++) {
            float gx = fmaf(2.0f, DB1[j], DB0[j] + DB2[j]);
            float gy = SB2[j] - SB0[j];
            float g2 = fmaf(gx, gx, fmaf(gy, gy, 1e-8f));
            float viol = fabsf(sqrt_approx(g2) - 1.0f);
            float msk  = (rvB[j] > 0.5f) ? 1.0f : 0.0f;
            lsum = fmaf(viol, msk, lsum);
            lcnt += msk;
        }

        #pragma unroll
        for (int j = 0; j < 4; j++) {
            SA0[j] = SA1[j]; SA1[j] = SA2[j];
            DA0[j] = DA1[j]; DA1[j] = DA2[j];
            SB0[j] = SB1[j]; SB1[j] = SB2[j];
            DB0[j] = DB1[j]; DB1[j] = DB2[j];
        }
    }

    // ---- block reduction (128 threads = 4 warps) ----
    #pragma unroll
    for (int off = 16; off > 0; off >>= 1) {
        lsum += __shfl_down_sync(0xFFFFFFFFu, lsum, off);
        lcnt += __shfl_down_sync(0xFFFFFFFFu, lcnt, off);
    }

    __shared__ float s_sum[4];
    __shared__ float s_cnt[4];
    const int wid = threadIdx.x >> 5;
    if (lane == 0) { s_sum[wid] = lsum; s_cnt[wid] = lcnt; }
    __syncthreads();

    __shared__ bool s_last;
    if (wid == 0) {
        lsum = (lane < 4) ? s_sum[lane] : 0.0f;
        lcnt = (lane < 4) ? s_cnt[lane] : 0.0f;
        #pragma unroll
        for (int off = 2; off > 0; off >>= 1) {
            lsum += __shfl_down_sync(0xFFFFFFFFu, lsum, off);
            lcnt += __shfl_down_sync(0xFFFFFFFFu, lcnt, off);
        }
        if (lane == 0) {
            g_part[blockIdx.x] = make_float2(lsum, lcnt);
            __threadfence();
            unsigned int prev = atomicAdd(&g_ticket, 1u);
            s_last = (prev == (unsigned int)(nBlocks - 1));
        }
    }
    __syncthreads();

    // ---- last block: reduce partials, write output, reset ticket ----
    if (s_last) {
        float fs = 0.0f, fc = 0.0f;
        for (int i = threadIdx.x; i < nBlocks; i += THREADS) {
            float2 v = g_part[i];
            fs += v.x;
            fc += v.y;
        }
        #pragma unroll
        for (int off = 16; off > 0; off >>= 1) {
            fs += __shfl_down_sync(0xFFFFFFFFu, fs, off);
            fc += __shfl_down_sync(0xFFFFFFFFu, fc, off);
        }
        if (lane == 0) { s_sum[wid] = fs; s_cnt[wid] = fc; }
        __syncthreads();
        if (threadIdx.x == 0) {
            fs = 0.0f; fc = 0.0f;
            #pragma unroll
            for (int i = 0; i < 4; i++) { fs += s_sum[i]; fc += s_cnt[i]; }
            out[0] = fs / fmaxf(fc, 1.0f);
            g_ticket = 0;   // reset for next graph replay
        }
    }
}

extern "C" void kernel_launch(void* const* d_in, const int* in_sizes, int n_in,
                              void* d_out, int out_size) {
    const float* pred  = (const float*)d_in[0];
    const float* reach = (const float*)d_in[1];
    float* out = (float*)d_out;

    const int total   = in_sizes[0];          // B*H*W
    const int B       = total / (H * W);
    const int nBlocks = B * 16;               // one strip pair per block

    eik_fused_kernel<<<nBlocks, THREADS>>>(pred, reach, out, nBlocks);
}